// round 4
// baseline (speedup 1.0000x reference)
#include <cuda_runtime.h>
#include <stdint.h>

#define NT 256
#define TILE 256        // points per block
#define KC 8            // k-chunk
#define NCHUNK 4        // 32 / KC

// Folded weights, each output value duplicated into an f32x2 pair.
// Pg[kj][o] as float2{v,v}; kj = k*6+j. 192*32*8 = 48 KB.
__device__ float2 Pg[192 * 32];

// Packed f32x2 FMA — only reachable via PTX (ptxas never emits FFMA2 from C++).
__device__ __forceinline__ long long fma2(long long a, long long b, long long c) {
    long long d;
    asm("fma.rn.f32x2 %0, %1, %2, %3;" : "=l"(d) : "l"(a), "l"(b), "l"(c));
    return d;
}

__global__ void hermite_prep(const float* __restrict__ sig,
                             const float* __restrict__ W) {
    int i = blockIdx.x * blockDim.x + threadIdx.x;   // 192*32 items
    if (i >= 192 * 32) return;
    int o  = i & 31;
    int kj = i >> 5;
    int k  = kj / 6;
    int j  = kj - k * 6;
    float val = 0.0f;
    if (o < 31) {
        float s   = sig[k];
        float s2  = s * s;
        float is2 = 1.0f / (s2 + 1e-6f);
        float is4 = 1.0f / (s2 * s2 + 1e-6f);
        const float* Wk = W + k * 186 + o;           // [k][h][o], H=6, O=31
        if      (j == 0) val = Wk[0] - is2 * (Wk[93] + Wk[155]);
        else if (j == 1) val = -is2 * Wk[62];        // * g*dx
        else if (j == 2) val = -is2 * Wk[31];        // * g*dy
        else if (j == 3) val = is4 * Wk[155];        // * g*dx^2
        else if (j == 4) val = is4 * Wk[124];        // * g*dx*dy
        else             val = is4 * Wk[93];         // * g*dy^2
    }
    Pg[kj * 32 + o] = make_float2(val, val);
}

extern __shared__ __align__(16) float smem[];
// smem: M[KC*6][TILE] floats = 49152 B; epilogue stage[256][33] (33792 B) reuses it.
#define SMEM_BYTES (KC * 6 * TILE * 4)

__global__ void __launch_bounds__(NT, 3)
hermite_main(const float* __restrict__ mlp,
             const float* __restrict__ cd,
             const float* __restrict__ gw,
             float* __restrict__ out,
             int total /* B*N */) {
    float* M = smem;
    const int tid   = threadIdx.x;
    const int tile0 = blockIdx.x * TILE;

    const int og  = tid & 3;          // outputs 8*og .. 8*og+7
    const int pg4 = (tid >> 2) * 4;   // first of 4 consecutive points

    long long acc[2][8];
#pragma unroll
    for (int pp = 0; pp < 2; pp++)
#pragma unroll
        for (int oo = 0; oo < 8; oo++) acc[pp][oo] = 0ll;

    const longlong2* PgLL = reinterpret_cast<const longlong2*>(Pg);

#pragma unroll 1
    for (int c = 0; c < NCHUNK; c++) {
        if (c > 0) __syncthreads();

        // ---- Phase 1: monomials for k in [c*KC, c*KC+KC) ----
        // lane->kl fastest: cd reads are 64B contiguous per point row.
        // STS col = pt ^ (kl<<2): 32 distinct banks per warp (conflict-free).
#pragma unroll
        for (int it = 0; it < (TILE * KC) / NT; it++) {   // 8 iters
            int item = tid + it * NT;
            int kl   = item & (KC - 1);
            int pt   = item >> 3;
            int n    = tile0 + pt;
            int k    = c * KC + kl;
            float dx = 0.0f, dy = 0.0f, g = 0.0f;
            if (n < total) {
                float2 cc = reinterpret_cast<const float2*>(cd)[(size_t)n * 32 + k];
                dx = cc.x; dy = cc.y;
                g  = gw[(size_t)n * 32 + k];
            }
            float m1 = g * dx, m2 = g * dy;
            float* Mr = M + (kl * 6) * TILE + (pt ^ (kl << 2));
            Mr[0 * TILE] = g;
            Mr[1 * TILE] = m1;
            Mr[2 * TILE] = m2;
            Mr[3 * TILE] = m1 * dx;
            Mr[4 * TILE] = m1 * dy;
            Mr[5 * TILE] = m2 * dy;
        }
        __syncthreads();

        // ---- Phase 2: 4 pts x 8 outs per thread ----
        // Per j: one LDS.128 (monomials, points packed) + 4 uniform LDG.128
        // (P from L1-resident global) + 16 FFMA2. Crossbar load = 50% of FMA.
#pragma unroll 2
        for (int kl = 0; kl < KC; kl++) {
            const float* Mk = M + (kl * 6) * TILE + (pg4 ^ (kl << 2));
            const longlong2* Pk = PgLL + ((c * KC + kl) * 6) * 16 + og * 4;
#pragma unroll
            for (int j = 0; j < 6; j++) {
                longlong2 mv = *reinterpret_cast<const longlong2*>(Mk + j * TILE);
                const longlong2* Pj = Pk + j * 16;
                longlong2 p0 = __ldg(Pj);
                longlong2 p1 = __ldg(Pj + 1);
                longlong2 p2 = __ldg(Pj + 2);
                longlong2 p3 = __ldg(Pj + 3);
                acc[0][0] = fma2(mv.x, p0.x, acc[0][0]);
                acc[0][1] = fma2(mv.x, p0.y, acc[0][1]);
                acc[0][2] = fma2(mv.x, p1.x, acc[0][2]);
                acc[0][3] = fma2(mv.x, p1.y, acc[0][3]);
                acc[0][4] = fma2(mv.x, p2.x, acc[0][4]);
                acc[0][5] = fma2(mv.x, p2.y, acc[0][5]);
                acc[0][6] = fma2(mv.x, p3.x, acc[0][6]);
                acc[0][7] = fma2(mv.x, p3.y, acc[0][7]);
                acc[1][0] = fma2(mv.y, p0.x, acc[1][0]);
                acc[1][1] = fma2(mv.y, p0.y, acc[1][1]);
                acc[1][2] = fma2(mv.y, p1.x, acc[1][2]);
                acc[1][3] = fma2(mv.y, p1.y, acc[1][3]);
                acc[1][4] = fma2(mv.y, p2.x, acc[1][4]);
                acc[1][5] = fma2(mv.y, p2.y, acc[1][5]);
                acc[1][6] = fma2(mv.y, p3.x, acc[1][6]);
                acc[1][7] = fma2(mv.y, p3.y, acc[1][7]);
            }
        }
    }

    // ---- Epilogue: stage mix (reuse M region), then coalesced I/O ----
    __syncthreads();
    float* stage = M;                 // [256][33]
#pragma unroll
    for (int pp = 0; pp < 2; pp++)
#pragma unroll
        for (int oo = 0; oo < 8; oo++) {
            long long a = acc[pp][oo];
            float lo = __uint_as_float((unsigned)((unsigned long long)a & 0xffffffffu));
            float hi = __uint_as_float((unsigned)((unsigned long long)a >> 32));
            int o = og * 8 + oo;
            stage[(pg4 + 2 * pp)     * 33 + o] = lo;
            stage[(pg4 + 2 * pp + 1) * 33 + o] = hi;
        }
    __syncthreads();

    size_t lim  = (size_t)total * 31;
    size_t base = (size_t)tile0 * 31;
    for (int e = tid; e < TILE * 31; e += NT) {
        size_t gidx = base + e;
        if (gidx < lim) {
            int rr = e / 31;
            int o  = e - rr * 31;
            out[gidx] = mlp[gidx] * stage[rr * 33 + o];
        }
    }
}

extern "C" void kernel_launch(void* const* d_in, const int* in_sizes, int n_in,
                              void* d_out, int out_size) {
    const float* mlp = (const float*)d_in[0];  // [B,N,31]
    const float* cd  = (const float*)d_in[1];  // [B,N,32,2]
    const float* sig = (const float*)d_in[2];  // [32]
    const float* gw  = (const float*)d_in[3];  // [B,N,32]
    const float* W   = (const float*)d_in[4];  // [32,6,31]

    int total  = in_sizes[3] / 32;             // B*N
    int blocks = (total + TILE - 1) / TILE;

    hermite_prep<<<(192 * 32 + 255) / 256, 256>>>(sig, W);

    cudaFuncSetAttribute(hermite_main,
                         cudaFuncAttributeMaxDynamicSharedMemorySize, SMEM_BYTES);
    hermite_main<<<blocks, NT, SMEM_BYTES>>>(mlp, cd, gw, (float*)d_out, total);
}

// round 5
// speedup vs baseline: 2.5986x; 2.5986x over previous
#include <cuda_runtime.h>
#include <stdint.h>

#define NT 128
#define TILE 256        // points per block
#define KC 8            // k-chunk
#define NCHUNK 4        // 32 / KC

// Raw folded weights P[kj][o], kj = k*6+j, o padded to 32. 24 KB.
__device__ float Pg[192 * 32];

// Packed f32x2 FMA — only via PTX (ptxas never emits FFMA2 from C++).
__device__ __forceinline__ long long fma2(long long a, long long b, long long c) {
    long long d;
    asm("fma.rn.f32x2 %0, %1, %2, %3;" : "=l"(d) : "l"(a), "l"(b), "l"(c));
    return d;
}
// Duplicate scalar into both halves of a 64-bit pair (ALU pipe, not crossbar).
__device__ __forceinline__ long long pack2(float x) {
    long long d;
    asm("mov.b64 %0, {%1, %1};" : "=l"(d) : "f"(x));
    return d;
}

__global__ void hermite_prep(const float* __restrict__ sig,
                             const float* __restrict__ W) {
    int i = blockIdx.x * blockDim.x + threadIdx.x;   // 192*32
    if (i >= 192 * 32) return;
    int o  = i & 31;
    int kj = i >> 5;
    int k  = kj / 6;
    int j  = kj - k * 6;
    float val = 0.0f;
    if (o < 31) {
        float s   = sig[k];
        float s2  = s * s;
        float is2 = 1.0f / (s2 + 1e-6f);
        float is4 = 1.0f / (s2 * s2 + 1e-6f);
        const float* Wk = W + k * 186 + o;           // [k][h][o], H=6, O=31
        if      (j == 0) val = Wk[0] - is2 * (Wk[93] + Wk[155]);
        else if (j == 1) val = -is2 * Wk[62];        // * g*dx
        else if (j == 2) val = -is2 * Wk[31];        // * g*dy
        else if (j == 3) val = is4 * Wk[155];        // * g*dx^2
        else if (j == 4) val = is4 * Wk[124];        // * g*dx*dy
        else             val = is4 * Wk[93];         // * g*dy^2
    }
    Pg[kj * 32 + o] = val;
}

extern __shared__ __align__(16) float smem[];
// M  : [KC*6][256] floats = 49152 B (xor-swizzled cols; epilogue stage reuses it)
// Psh: [192][32]  floats  = 24576 B (raw)
#define M_FLOATS (KC * 6 * TILE)
#define SMEM_BYTES (M_FLOATS * 4 + 192 * 32 * 4)

__global__ void __launch_bounds__(NT, 3)
hermite_main(const float* __restrict__ mlp,
             const float* __restrict__ cd,
             const float* __restrict__ gw,
             float* __restrict__ out,
             int total /* B*N */) {
    float* M   = smem;
    float* Psh = smem + M_FLOATS;

    const int tid   = threadIdx.x;
    const int tile0 = blockIdx.x * TILE;

    // ---- Load raw P into SMEM (coalesced, 12 float4 per thread) ----
    {
        const float4* src = reinterpret_cast<const float4*>(Pg);
        float4*       dst = reinterpret_cast<float4*>(Psh);
        for (int i = tid; i < (192 * 32) / 4; i += NT) dst[i] = src[i];
    }

    const int og  = tid & 3;          // outputs og*8 .. og*8+7
    const int pg8 = (tid >> 2) * 8;   // first of 8 consecutive points

    long long acc[4][8];
#pragma unroll
    for (int pp = 0; pp < 4; pp++)
#pragma unroll
        for (int oo = 0; oo < 8; oo++) acc[pp][oo] = 0ll;

#pragma unroll 1
    for (int c = 0; c < NCHUNK; c++) {
        __syncthreads();   // P ready (c=0) / previous chunk's M reads done

        // ---- Phase 1: monomials for k in [c*KC, c*KC+KC) ----
        // lane->kl fastest (coalesced 64B cd segments); STS col = pt^(kl<<2)
        // gives 32 distinct banks per warp (conflict-free).
#pragma unroll
        for (int it = 0; it < (TILE * KC) / NT; it++) {   // 16 iters
            int item = tid + it * NT;
            int kl   = item & (KC - 1);
            int pt   = item >> 3;
            int n    = tile0 + pt;
            int k    = c * KC + kl;
            float dx = 0.0f, dy = 0.0f, g = 0.0f;
            if (n < total) {
                float2 cc = reinterpret_cast<const float2*>(cd)[(size_t)n * 32 + k];
                dx = cc.x; dy = cc.y;
                g  = gw[(size_t)n * 32 + k];
            }
            float m1 = g * dx, m2 = g * dy;
            float* Mr = M + (kl * 6) * TILE + (pt ^ (kl << 2));
            Mr[0 * TILE] = g;
            Mr[1 * TILE] = m1;
            Mr[2 * TILE] = m2;
            Mr[3 * TILE] = m1 * dx;
            Mr[4 * TILE] = m1 * dy;
            Mr[5 * TILE] = m2 * dy;
        }
        __syncthreads();

        // ---- Phase 2: 8 pts x 8 outs per thread ----
        // Per j: 2 LDS.128 M (8 wf) + 2 LDS.128 raw P (8 wf) + 8 ALU packs
        // + 32 FFMA2 (16 SM-cyc). Crossbar : FMA = 16 : 16 — balanced.
#pragma unroll 2
        for (int kl = 0; kl < KC; kl++) {
            const int   sw = kl << 2;
            const float* Mk = M + (kl * 6) * TILE;
            const float4* Pk =
                reinterpret_cast<const float4*>(Psh + ((c * KC + kl) * 6) * 32) + og * 2;
#pragma unroll
            for (int j = 0; j < 6; j++) {
                float4 ma = *reinterpret_cast<const float4*>(Mk + j * TILE + (pg8 ^ sw));
                float4 mb = *reinterpret_cast<const float4*>(Mk + j * TILE + ((pg8 + 4) ^ sw));
                float4 pa = Pk[j * 8];
                float4 pb = Pk[j * 8 + 1];

                long long mv0 = *reinterpret_cast<long long*>(&ma.x);
                long long mv1 = *reinterpret_cast<long long*>(&ma.z);
                long long mv2 = *reinterpret_cast<long long*>(&mb.x);
                long long mv3 = *reinterpret_cast<long long*>(&mb.z);

                long long pd[8];
                pd[0] = pack2(pa.x); pd[1] = pack2(pa.y);
                pd[2] = pack2(pa.z); pd[3] = pack2(pa.w);
                pd[4] = pack2(pb.x); pd[5] = pack2(pb.y);
                pd[6] = pack2(pb.z); pd[7] = pack2(pb.w);

#pragma unroll
                for (int oo = 0; oo < 8; oo++) {
                    acc[0][oo] = fma2(mv0, pd[oo], acc[0][oo]);
                    acc[1][oo] = fma2(mv1, pd[oo], acc[1][oo]);
                    acc[2][oo] = fma2(mv2, pd[oo], acc[2][oo]);
                    acc[3][oo] = fma2(mv3, pd[oo], acc[3][oo]);
                }
            }
        }
    }

    // ---- Epilogue: stage mix (reuse M region), then coalesced I/O ----
    __syncthreads();
    float* stage = M;                 // [256][33]
#pragma unroll
    for (int pp = 0; pp < 4; pp++)
#pragma unroll
        for (int oo = 0; oo < 8; oo++) {
            long long a = acc[pp][oo];
            float lo = __uint_as_float((unsigned)((unsigned long long)a & 0xffffffffu));
            float hi = __uint_as_float((unsigned)((unsigned long long)a >> 32));
            int o = og * 8 + oo;
            stage[(pg8 + 2 * pp)     * 33 + o] = lo;
            stage[(pg8 + 2 * pp + 1) * 33 + o] = hi;
        }
    __syncthreads();

    size_t lim  = (size_t)total * 31;
    size_t base = (size_t)tile0 * 31;
    for (int e = tid; e < TILE * 31; e += NT) {
        size_t gidx = base + e;
        if (gidx < lim) {
            int rr = e / 31;
            int o  = e - rr * 31;
            out[gidx] = mlp[gidx] * stage[rr * 33 + o];
        }
    }
}

extern "C" void kernel_launch(void* const* d_in, const int* in_sizes, int n_in,
                              void* d_out, int out_size) {
    const float* mlp = (const float*)d_in[0];  // [B,N,31]
    const float* cd  = (const float*)d_in[1];  // [B,N,32,2]
    const float* sig = (const float*)d_in[2];  // [32]
    const float* gw  = (const float*)d_in[3];  // [B,N,32]
    const float* W   = (const float*)d_in[4];  // [32,6,31]

    int total  = in_sizes[3] / 32;             // B*N
    int blocks = (total + TILE - 1) / TILE;    // 1024

    hermite_prep<<<(192 * 32 + 255) / 256, 256>>>(sig, W);

    cudaFuncSetAttribute(hermite_main,
                         cudaFuncAttributeMaxDynamicSharedMemorySize, SMEM_BYTES);
    hermite_main<<<blocks, NT, SMEM_BYTES>>>(mlp, cd, gw, (float*)d_out, total);
}

// round 7
// speedup vs baseline: 2.7529x; 1.0594x over previous
#include <cuda_runtime.h>
#include <stdint.h>

#define NT 128
#define TILE 256        // points per block
#define KC 4            // k-chunk
#define NCHUNK 8        // 32 / KC

// Raw folded weights P[kj][o], kj = k*6+j, o padded to 32. 24 KB.
__device__ float Pg[192 * 32];

// Packed f32x2 FMA — only via PTX (ptxas never emits FFMA2 from C++).
__device__ __forceinline__ long long fma2(long long a, long long b, long long c) {
    long long d;
    asm("fma.rn.f32x2 %0, %1, %2, %3;" : "=l"(d) : "l"(a), "l"(b), "l"(c));
    return d;
}
// Duplicate scalar into both halves of a 64-bit pair (ALU pipe, not crossbar).
__device__ __forceinline__ long long pack2(float x) {
    long long d;
    asm("mov.b64 %0, {%1, %1};" : "=l"(d) : "f"(x));
    return d;
}

__global__ void hermite_prep(const float* __restrict__ sig,
                             const float* __restrict__ W) {
    int i = blockIdx.x * blockDim.x + threadIdx.x;   // 192*32
    if (i >= 192 * 32) return;
    int o  = i & 31;
    int kj = i >> 5;
    int k  = kj / 6;
    int j  = kj - k * 6;
    float val = 0.0f;
    if (o < 31) {
        float s   = sig[k];
        float s2  = s * s;
        float is2 = 1.0f / (s2 + 1e-6f);
        float is4 = 1.0f / (s2 * s2 + 1e-6f);
        const float* Wk = W + k * 186 + o;           // [k][h][o], H=6, O=31
        if      (j == 0) val = Wk[0] - is2 * (Wk[93] + Wk[155]);
        else if (j == 1) val = -is2 * Wk[62];        // * g*dx
        else if (j == 2) val = -is2 * Wk[31];        // * g*dy
        else if (j == 3) val = is4 * Wk[155];        // * g*dx^2
        else if (j == 4) val = is4 * Wk[124];        // * g*dx*dy
        else             val = is4 * Wk[93];         // * g*dy^2
    }
    Pg[kj * 32 + o] = val;
}

extern __shared__ __align__(16) float smem[];
// M  : [KC*6][256] floats = 24576 B (xor-swizzled cols)
// Psh: [192][32]  floats  = 24576 B (raw)
// epilogue stage[256][33] = 33792 B reuses M+Psh (both dead by then)
#define M_FLOATS (KC * 6 * TILE)
#define SMEM_BYTES (M_FLOATS * 4 + 192 * 32 * 4)

__global__ void __launch_bounds__(NT, 4)
hermite_main(const float* __restrict__ mlp,
             const float* __restrict__ cd,
             const float* __restrict__ gw,
             float* __restrict__ out,
             int total /* B*N */) {
    float* M   = smem;
    float* Psh = smem + M_FLOATS;

    const int tid   = threadIdx.x;
    const int tile0 = blockIdx.x * TILE;

    // ---- Load raw P into SMEM (coalesced, 12 float4 per thread) ----
    {
        const float4* src = reinterpret_cast<const float4*>(Pg);
        float4*       dst = reinterpret_cast<float4*>(Psh);
        for (int i = tid; i < (192 * 32) / 4; i += NT) dst[i] = src[i];
    }

    const int og  = tid & 3;          // outputs og*8 .. og*8+7
    const int pg8 = (tid >> 2) * 8;   // first of 8 consecutive points

    long long acc[4][8];
#pragma unroll
    for (int pp = 0; pp < 4; pp++)
#pragma unroll
        for (int oo = 0; oo < 8; oo++) acc[pp][oo] = 0ll;

#pragma unroll 1
    for (int c = 0; c < NCHUNK; c++) {
        __syncthreads();   // P ready (c=0) / previous chunk's M reads done

        // ---- Phase 1: monomials for k in [c*KC, c*KC+KC) ----
        // lane->kl fastest; STS col = pt ^ (kl<<3): kl occupies bits 3-4,
        // pt bits 0-2 within a warp -> 32 distinct banks (conflict-free).
#pragma unroll
        for (int it = 0; it < (TILE * KC) / NT; it++) {   // 8 iters
            int item = tid + it * NT;
            int kl   = item & (KC - 1);
            int pt   = item >> 2;
            int n    = tile0 + pt;
            int k    = c * KC + kl;
            float dx = 0.0f, dy = 0.0f, g = 0.0f;
            if (n < total) {
                float2 cc = reinterpret_cast<const float2*>(cd)[(size_t)n * 32 + k];
                dx = cc.x; dy = cc.y;
                g  = gw[(size_t)n * 32 + k];
            }
            float m1 = g * dx, m2 = g * dy;
            float* Mr = M + (kl * 6) * TILE + (pt ^ (kl << 3));
            Mr[0 * TILE] = g;
            Mr[1 * TILE] = m1;
            Mr[2 * TILE] = m2;
            Mr[3 * TILE] = m1 * dx;
            Mr[4 * TILE] = m1 * dy;
            Mr[5 * TILE] = m2 * dy;
        }
        __syncthreads();

        // ---- Phase 2: 8 pts x 8 outs per thread ----
        // Per j: 2 LDS.128 M (8 wf) + 2 LDS.128 raw P (8 wf) + 8 ALU packs
        // + 32 FFMA2 (16 SM-cyc). Crossbar : FMA = 16 : 16 — balanced.
#pragma unroll 1
        for (int kl = 0; kl < KC; kl++) {
            const int    sw = kl << 3;
            const float* Mk = M + (kl * 6) * TILE;
            const float4* Pk =
                reinterpret_cast<const float4*>(Psh + ((c * KC + kl) * 6) * 32) + og * 2;
#pragma unroll
            for (int j = 0; j < 6; j++) {
                float4 ma = *reinterpret_cast<const float4*>(Mk + j * TILE + (pg8 ^ sw));
                float4 mb = *reinterpret_cast<const float4*>(Mk + j * TILE + ((pg8 + 4) ^ sw));
                float4 pa = Pk[j * 8];
                float4 pb = Pk[j * 8 + 1];

                long long mv0 = *reinterpret_cast<long long*>(&ma.x);
                long long mv1 = *reinterpret_cast<long long*>(&ma.z);
                long long mv2 = *reinterpret_cast<long long*>(&mb.x);
                long long mv3 = *reinterpret_cast<long long*>(&mb.z);

                long long pd[8];
                pd[0] = pack2(pa.x); pd[1] = pack2(pa.y);
                pd[2] = pack2(pa.z); pd[3] = pack2(pa.w);
                pd[4] = pack2(pb.x); pd[5] = pack2(pb.y);
                pd[6] = pack2(pb.z); pd[7] = pack2(pb.w);

#pragma unroll
                for (int oo = 0; oo < 8; oo++) {
                    acc[0][oo] = fma2(mv0, pd[oo], acc[0][oo]);
                    acc[1][oo] = fma2(mv1, pd[oo], acc[1][oo]);
                    acc[2][oo] = fma2(mv2, pd[oo], acc[2][oo]);
                    acc[3][oo] = fma2(mv3, pd[oo], acc[3][oo]);
                }
            }
        }
    }

    // ---- Epilogue: stage mix (reuse whole smem), then coalesced I/O ----
    __syncthreads();
    float* stage = smem;              // [256][33] = 33792 B <= 49152 B
#pragma unroll
    for (int pp = 0; pp < 4; pp++)
#pragma unroll
        for (int oo = 0; oo < 8; oo++) {
            long long a = acc[pp][oo];
            float lo = __uint_as_float((unsigned)((unsigned long long)a & 0xffffffffu));
            float hi = __uint_as_float((unsigned)((unsigned long long)a >> 32));
            int o = og * 8 + oo;
            stage[(pg8 + 2 * pp)     * 33 + o] = lo;
            stage[(pg8 + 2 * pp + 1) * 33 + o] = hi;
        }
    __syncthreads();

    size_t lim  = (size_t)total * 31;
    size_t base = (size_t)tile0 * 31;
    for (int e = tid; e < TILE * 31; e += NT) {
        size_t gidx = base + e;
        if (gidx < lim) {
            int rr = e / 31;
            int o  = e - rr * 31;
            out[gidx] = mlp[gidx] * stage[rr * 33 + o];
        }
    }
}

extern "C" void kernel_launch(void* const* d_in, const int* in_sizes, int n_in,
                              void* d_out, int out_size) {
    const float* mlp = (const float*)d_in[0];  // [B,N,31]
    const float* cd  = (const float*)d_in[1];  // [B,N,32,2]
    const float* sig = (const float*)d_in[2];  // [32]
    const float* gw  = (const float*)d_in[3];  // [B,N,32]
    const float* W   = (const float*)d_in[4];  // [32,6,31]

    int total  = in_sizes[3] / 32;             // B*N
    int blocks = (total + TILE - 1) / TILE;    // 1024

    hermite_prep<<<(192 * 32 + 255) / 256, 256>>>(sig, W);

    cudaFuncSetAttribute(hermite_main,
                         cudaFuncAttributeMaxDynamicSharedMemorySize, SMEM_BYTES);
    hermite_main<<<blocks, NT, SMEM_BYTES>>>(mlp, cd, gw, (float*)d_out, total);
}

// round 8
// speedup vs baseline: 2.8697x; 1.0424x over previous
#include <cuda_runtime.h>
#include <stdint.h>

#define NT 128
#define TILE 256        // points per block
#define KC 8            // k-chunk
#define NCHUNK 4        // 32 / KC

// Raw folded weights P[kj][o], kj = k*6+j, o padded to 32. 24 KB.
__device__ float Pg[192 * 32];

__device__ __forceinline__ long long fma2(long long a, long long b, long long c) {
    long long d;
    asm("fma.rn.f32x2 %0, %1, %2, %3;" : "=l"(d) : "l"(a), "l"(b), "l"(c));
    return d;
}
__device__ __forceinline__ long long mul2(long long a, long long b) {
    long long d;
    asm("mul.rn.f32x2 %0, %1, %2;" : "=l"(d) : "l"(a), "l"(b));
    return d;
}
__device__ __forceinline__ long long pack2(float x) {
    long long d;
    asm("mov.b64 %0, {%1, %1};" : "=l"(d) : "f"(x));
    return d;
}
#define LL(f4, half) (*reinterpret_cast<const long long*>(&(f4).half))

__global__ void hermite_prep(const float* __restrict__ sig,
                             const float* __restrict__ W) {
    int i = blockIdx.x * blockDim.x + threadIdx.x;
    if (i >= 192 * 32) return;
    int o  = i & 31;
    int kj = i >> 5;
    int k  = kj / 6;
    int j  = kj - k * 6;
    float val = 0.0f;
    if (o < 31) {
        float s   = sig[k];
        float s2  = s * s;
        float is2 = 1.0f / (s2 + 1e-6f);
        float is4 = 1.0f / (s2 * s2 + 1e-6f);
        const float* Wk = W + k * 186 + o;           // [k][h][o], H=6, O=31
        if      (j == 0) val = Wk[0] - is2 * (Wk[93] + Wk[155]);
        else if (j == 1) val = -is2 * Wk[62];        // * g*dx
        else if (j == 2) val = -is2 * Wk[31];        // * g*dy
        else if (j == 3) val = is4 * Wk[155];        // * g*dx^2
        else if (j == 4) val = is4 * Wk[124];        // * g*dx*dy
        else             val = is4 * Wk[93];         // * g*dy^2
    }
    Pg[kj * 32 + o] = val;
}

extern __shared__ __align__(16) float smem[];
// dxs/dys/gs : [KC][256] each (8192 B x3 = 24576 B), swizzled cols
// Psh        : [192][32] raw  (24576 B)
// epilogue stage[256][33] (33792 B) reuses dxs/dys/gs + part of Psh
#define RAW_FLOATS (KC * TILE)
#define SMEM_BYTES (3 * RAW_FLOATS * 4 + 192 * 32 * 4)

// swizzle: keeps 16B granularity; kills stride-32B phase conflicts (p-term)
// and row-vs-row STS conflicts (kl-term).
__device__ __forceinline__ int swz(int p, int kl) {
    return p ^ ((p & 32) >> 3) ^ (kl << 2);
}

__global__ void __launch_bounds__(NT, 4)
hermite_main(const float* __restrict__ mlp,
             const float* __restrict__ cd,
             const float* __restrict__ gw,
             float* __restrict__ out,
             int total /* B*N */) {
    float* dxs = smem;
    float* dys = smem + RAW_FLOATS;
    float* gs  = smem + 2 * RAW_FLOATS;
    float* Psh = smem + 3 * RAW_FLOATS;

    const int tid   = threadIdx.x;
    const int wid   = tid >> 5;        // o-group: outputs wid*8 .. wid*8+7
    const int lane  = tid & 31;
    const int pg8   = lane * 8;        // this thread's 8 points
    const int tile0 = blockIdx.x * TILE;

    // ---- Load raw P into SMEM (coalesced) ----
    {
        const float4* src = reinterpret_cast<const float4*>(Pg);
        float4*       dst = reinterpret_cast<float4*>(Psh);
        for (int i = tid; i < (192 * 32) / 4; i += NT) dst[i] = src[i];
    }

    long long acc[4][8];
#pragma unroll
    for (int pp = 0; pp < 4; pp++)
#pragma unroll
        for (int oo = 0; oo < 8; oo++) acc[pp][oo] = 0ll;

#pragma unroll 1
    for (int c = 0; c < NCHUNK; c++) {
        __syncthreads();   // P ready (c=0) / previous chunk's reads done

        // ---- Phase 1: stage raw dx,dy,g for k in [c*KC, c*KC+KC) ----
        // lane->kl fastest (coalesced 64B cd segments); swz gives 32 distinct
        // banks per warp for each STS.
#pragma unroll
        for (int it = 0; it < (TILE * KC) / NT; it++) {   // 16 iters
            int item = tid + it * NT;
            int kl   = item & (KC - 1);
            int pt   = item >> 3;
            int n    = tile0 + pt;
            int k    = c * KC + kl;
            float dx = 0.0f, dy = 0.0f, g = 0.0f;
            if (n < total) {
                float2 cc = reinterpret_cast<const float2*>(cd)[(size_t)n * 32 + k];
                dx = cc.x; dy = cc.y;
                g  = gw[(size_t)n * 32 + k];
            }
            int col = swz(pt, kl);
            dxs[kl * TILE + col] = dx;
            dys[kl * TILE + col] = dy;
            gs [kl * TILE + col] = g;
        }
        __syncthreads();

        // ---- Phase 2: 8 pts x 8 outs; P loads warp-uniform ----
#pragma unroll 1
        for (int kl = 0; kl < KC; kl++) {
            int colA = swz(pg8, kl);
            int colB = swz(pg8 + 4, kl);
            float4 ga  = *reinterpret_cast<const float4*>(gs  + kl * TILE + colA);
            float4 gb  = *reinterpret_cast<const float4*>(gs  + kl * TILE + colB);
            float4 dxa = *reinterpret_cast<const float4*>(dxs + kl * TILE + colA);
            float4 dxb = *reinterpret_cast<const float4*>(dxs + kl * TILE + colB);
            float4 dya = *reinterpret_cast<const float4*>(dys + kl * TILE + colA);
            float4 dyb = *reinterpret_cast<const float4*>(dys + kl * TILE + colB);

            long long gp[4]  = { LL(ga, x), LL(ga, z), LL(gb, x), LL(gb, z) };
            long long dxp[4] = { LL(dxa, x), LL(dxa, z), LL(dxb, x), LL(dxb, z) };
            long long dyp[4] = { LL(dya, x), LL(dya, z), LL(dyb, x), LL(dyb, z) };

            const float* Pj = Psh + ((c * KC + kl) * 6) * 32 + wid * 8;

#define DO_J(jj, MV) do {                                                      \
    float4 pa = *reinterpret_cast<const float4*>(Pj + (jj) * 32);              \
    float4 pb = *reinterpret_cast<const float4*>(Pj + (jj) * 32 + 4);          \
    const float* pf = &pa.x;                                                   \
    _Pragma("unroll")                                                          \
    for (int oo = 0; oo < 4; oo++) {                                           \
        long long pd = pack2(pf[oo]);                                          \
        acc[0][oo] = fma2((MV)[0], pd, acc[0][oo]);                            \
        acc[1][oo] = fma2((MV)[1], pd, acc[1][oo]);                            \
        acc[2][oo] = fma2((MV)[2], pd, acc[2][oo]);                            \
        acc[3][oo] = fma2((MV)[3], pd, acc[3][oo]);                            \
    }                                                                          \
    const float* pg = &pb.x;                                                   \
    _Pragma("unroll")                                                          \
    for (int oo = 0; oo < 4; oo++) {                                           \
        long long pd = pack2(pg[oo]);                                          \
        acc[0][4 + oo] = fma2((MV)[0], pd, acc[0][4 + oo]);                    \
        acc[1][4 + oo] = fma2((MV)[1], pd, acc[1][4 + oo]);                    \
        acc[2][4 + oo] = fma2((MV)[2], pd, acc[2][4 + oo]);                    \
        acc[3][4 + oo] = fma2((MV)[3], pd, acc[3][4 + oo]);                    \
    }                                                                          \
} while (0)

            DO_J(0, gp);                           // coeff 1
            long long m1[4];
#pragma unroll
            for (int pp = 0; pp < 4; pp++) m1[pp] = mul2(gp[pp], dxp[pp]);
            DO_J(1, m1);                           // g*dx
            long long m2[4];
#pragma unroll
            for (int pp = 0; pp < 4; pp++) m2[pp] = mul2(gp[pp], dyp[pp]);
            DO_J(2, m2);                           // g*dy
            long long mt[4];
#pragma unroll
            for (int pp = 0; pp < 4; pp++) mt[pp] = mul2(m1[pp], dxp[pp]);
            DO_J(3, mt);                           // g*dx^2
#pragma unroll
            for (int pp = 0; pp < 4; pp++) mt[pp] = mul2(m1[pp], dyp[pp]);
            DO_J(4, mt);                           // g*dx*dy
#pragma unroll
            for (int pp = 0; pp < 4; pp++) mt[pp] = mul2(m2[pp], dyp[pp]);
            DO_J(5, mt);                           // g*dy^2
#undef DO_J
        }
    }

    // ---- Epilogue: stage mix (reuse smem), then coalesced I/O ----
    __syncthreads();
    float* stage = smem;              // [256][33] = 33792 B
#pragma unroll
    for (int pp = 0; pp < 4; pp++)
#pragma unroll
        for (int oo = 0; oo < 8; oo++) {
            long long a = acc[pp][oo];
            float lo = __uint_as_float((unsigned)((unsigned long long)a & 0xffffffffu));
            float hi = __uint_as_float((unsigned)((unsigned long long)a >> 32));
            int o = wid * 8 + oo;
            stage[(pg8 + 2 * pp)     * 33 + o] = lo;
            stage[(pg8 + 2 * pp + 1) * 33 + o] = hi;
        }
    __syncthreads();

    size_t lim  = (size_t)total * 31;
    size_t base = (size_t)tile0 * 31;
    for (int e = tid; e < TILE * 31; e += NT) {
        size_t gidx = base + e;
        if (gidx < lim) {
            int rr = e / 31;
            int o  = e - rr * 31;
            out[gidx] = mlp[gidx] * stage[rr * 33 + o];
        }
    }
}

extern "C" void kernel_launch(void* const* d_in, const int* in_sizes, int n_in,
                              void* d_out, int out_size) {
    const float* mlp = (const float*)d_in[0];  // [B,N,31]
    const float* cd  = (const float*)d_in[1];  // [B,N,32,2]
    const float* sig = (const float*)d_in[2];  // [32]
    const float* gw  = (const float*)d_in[3];  // [B,N,32]
    const float* W   = (const float*)d_in[4];  // [32,6,31]

    int total  = in_sizes[3] / 32;             // B*N
    int blocks = (total + TILE - 1) / TILE;    // 1024

    hermite_prep<<<(192 * 32 + 255) / 256, 256>>>(sig, W);

    cudaFuncSetAttribute(hermite_main,
                         cudaFuncAttributeMaxDynamicSharedMemorySize, SMEM_BYTES);
    hermite_main<<<blocks, NT, SMEM_BYTES>>>(mlp, cd, gw, (float*)d_out, total);
}